// round 1
// baseline (speedup 1.0000x reference)
#include <cuda_runtime.h>

// Problem constants (fixed by the dataset)
#define N_NODES 32
#define M_EDGES 256
#define D_EMB   32
#define H1 128   // layer-1 width (= 4*d)
#define H2 256
#define H3 128
#define NPAIR 1024          // n*n
#define TM 64               // edge rows per CTA tile
#define HS_PAD 68           // padded row stride for Hs (float4-aligned, reduces conflicts)
#define EPSF 1e-9f

// ---------------- scratch (no allocations allowed) ----------------
__device__ float g_aT[H1 * N_NODES];    // a[k][s]  : emb[s] @ W1[0:32]
__device__ float g_bT[H1 * N_NODES];    // b[k][t]  : emb[t] @ W1[32:64]
__device__ float g_cT[H1 * M_EDGES];    // c[k][e]  : emb[u]@W1[64:96] + emb[v]@W1[96:128] + b1
__device__ float g_preds[NPAIR * M_EDGES];
__device__ float g_A[NPAIR * N_NODES * N_NODES];
__device__ float g_delta[NPAIR * N_NODES];

// ---------------- kernel 1: factored layer-1 partials ----------------
// grid 160 x 256 = 40960 threads exactly (4096 + 4096 + 32768)
__global__ void prep_kernel(const float* __restrict__ emb,
                            const int*   __restrict__ edges,
                            const float* __restrict__ W1,
                            const float* __restrict__ b1)
{
    int idx = blockIdx.x * blockDim.x + threadIdx.x;
    if (idx < 2 * H1 * N_NODES) {
        int sec = idx >> 12;            // 0: aT, 1: bT
        int r   = idx & 4095;
        int k = r >> 5, s = r & 31;
        const float* w = W1 + (sec ? (32 * H1) : 0) + k;
        float acc = 0.f;
        #pragma unroll
        for (int j = 0; j < D_EMB; j++)
            acc = fmaf(emb[s * D_EMB + j], w[j * H1], acc);
        (sec ? g_bT : g_aT)[k * N_NODES + s] = acc;
    } else {
        int r = idx - 2 * H1 * N_NODES;       // [0, 32768)
        int k = r >> 8, e = r & 255;
        int u = edges[2 * e], v = edges[2 * e + 1];
        const float* wu = W1 + 64 * H1 + k;
        const float* wv = W1 + 96 * H1 + k;
        float acc = b1[k];
        #pragma unroll
        for (int j = 0; j < D_EMB; j++) {
            acc = fmaf(emb[u * D_EMB + j], wu[j * H1], acc);
            acc = fmaf(emb[v * D_EMB + j], wv[j * H1], acc);
        }
        g_cT[k * M_EDGES + e] = acc;
    }
}

// ---------------- kernel 2: fused MLP (layers 2,3,4) ----------------
// One CTA = one (s,t) pair x 64 edge rows.  grid = 1024*4 = 4096, 256 threads.
// Thread grid 16(tm) x 16(tn); micro-tile 4 rows x 8 cols.
//   tm = tid & 15  -> rows tm*4 .. tm*4+3
//   tn = tid >> 4  -> cols tn*8 .. tn*8+7
__global__ void __launch_bounds__(256)
mlp_kernel(const float* __restrict__ W2, const float* __restrict__ b2,
           const float* __restrict__ W3, const float* __restrict__ b3,
           const float* __restrict__ W4, const float* __restrict__ b4)
{
    __shared__ float Hs[H1][HS_PAD];    // K x M activation tile (h1, then h2 chunk)
    __shared__ float Bs[8][128];        // K-slice of weights
    __shared__ float red[16][64];       // layer-4 reduction

    const int tid  = threadIdx.x;
    const int tm   = tid & 15;
    const int tn   = tid >> 4;
    const int bid  = blockIdx.x;
    const int pair = bid >> 2;
    const int eb   = (bid & 3) * TM;
    const int s    = pair >> 5;
    const int t    = pair & 31;

    float acc3[4][8];
    #pragma unroll
    for (int i = 0; i < 4; i++)
        #pragma unroll
        for (int j = 0; j < 8; j++) acc3[i][j] = 0.f;

    for (int kc = 0; kc < 2; kc++) {
        // ---- (re)build h1 tile:  Hs[k][row] = relu(a[s][k]+b[t][k]+c[e][k]) ----
        __syncthreads();   // previous chunk done reading Hs
        #pragma unroll 4
        for (int i = tid; i < H1 * TM; i += 256) {
            int k = i >> 6, row = i & 63;
            float v = g_aT[k * N_NODES + s] + g_bT[k * N_NODES + t]
                    + g_cT[k * M_EDGES + eb + row];
            Hs[k][row] = fmaxf(v, 0.f);
        }

        // ---- layer 2 chunk:  acc2 = h1 @ W2[:, kc*128 : kc*128+128] ----
        float acc2[4][8];
        #pragma unroll
        for (int i = 0; i < 4; i++)
            #pragma unroll
            for (int j = 0; j < 8; j++) acc2[i][j] = 0.f;

        const float* gB2 = W2 + kc * 128;
        for (int k0 = 0; k0 < H1; k0 += 8) {
            __syncthreads();
            *(float4*)&Bs[tid >> 5][(tid & 31) * 4] =
                *(const float4*)(gB2 + (k0 + (tid >> 5)) * H2 + (tid & 31) * 4);
            __syncthreads();
            #pragma unroll
            for (int kk = 0; kk < 8; kk++) {
                float4 a4 = *(const float4*)&Hs[k0 + kk][tm * 4];
                float av[4] = {a4.x, a4.y, a4.z, a4.w};
                float bv[8];
                *(float4*)&bv[0] = *(const float4*)&Bs[kk][tn * 8];
                *(float4*)&bv[4] = *(const float4*)&Bs[kk][tn * 8 + 4];
                #pragma unroll
                for (int i = 0; i < 4; i++)
                    #pragma unroll
                    for (int j = 0; j < 8; j++)
                        acc2[i][j] = fmaf(av[i], bv[j], acc2[i][j]);
            }
        }

        // ---- epilogue: h2 chunk -> Hs (transposed store, K2 x M) ----
        __syncthreads();   // everyone done reading h1
        #pragma unroll
        for (int j = 0; j < 8; j++) {
            float bj = b2[kc * 128 + tn * 8 + j];
            #pragma unroll
            for (int i = 0; i < 4; i++)
                Hs[tn * 8 + j][tm * 4 + i] = fmaxf(acc2[i][j] + bj, 0.f);
        }

        // ---- layer 3 chunk:  acc3 += h2c @ W3[kc*128 : kc*128+128, :] ----
        const float* gB3 = W3 + kc * 128 * H3;
        for (int k0 = 0; k0 < 128; k0 += 8) {
            __syncthreads();
            *(float4*)&Bs[tid >> 5][(tid & 31) * 4] =
                *(const float4*)(gB3 + (k0 + (tid >> 5)) * H3 + (tid & 31) * 4);
            __syncthreads();
            #pragma unroll
            for (int kk = 0; kk < 8; kk++) {
                float4 a4 = *(const float4*)&Hs[k0 + kk][tm * 4];
                float av[4] = {a4.x, a4.y, a4.z, a4.w};
                float bv[8];
                *(float4*)&bv[0] = *(const float4*)&Bs[kk][tn * 8];
                *(float4*)&bv[4] = *(const float4*)&Bs[kk][tn * 8 + 4];
                #pragma unroll
                for (int i = 0; i < 4; i++)
                    #pragma unroll
                    for (int j = 0; j < 8; j++)
                        acc3[i][j] = fmaf(av[i], bv[j], acc3[i][j]);
            }
        }
    }

    // ---- layer 4: pred = relu(h3) @ W4 + b4, reduce over tn via smem ----
    float part[4] = {0.f, 0.f, 0.f, 0.f};
    #pragma unroll
    for (int j = 0; j < 8; j++) {
        float b3j = b3[tn * 8 + j];
        float w4j = W4[tn * 8 + j];
        #pragma unroll
        for (int i = 0; i < 4; i++)
            part[i] = fmaf(fmaxf(acc3[i][j] + b3j, 0.f), w4j, part[i]);
    }
    __syncthreads();
    #pragma unroll
    for (int i = 0; i < 4; i++) red[tn][tm * 4 + i] = part[i];
    __syncthreads();
    #pragma unroll
    for (int st = 8; st > 0; st >>= 1) {
        if (tn < st) {
            #pragma unroll
            for (int i = 0; i < 4; i++)
                red[tn][tm * 4 + i] += red[tn + st][tm * 4 + i];
        }
        __syncthreads();
    }
    if (tn == 0) {
        float b4v = b4[0];
        #pragma unroll
        for (int i = 0; i < 4; i++)
            g_preds[pair * M_EDGES + eb + tm * 4 + i] = red[0][tm * 4 + i] + b4v;
    }
}

// ---------------- kernel 3: scatter preds into routing matrices ----------------
// grid = 1024 (one CTA per (s,t) pair), 256 threads (one per edge)
__global__ void scatter_kernel(const int* __restrict__ edges)
{
    __shared__ float As[N_NODES * N_NODES];
    int p = blockIdx.x, tid = threadIdx.x;
    #pragma unroll
    for (int i = tid; i < 1024; i += 256) As[i] = 0.f;
    __syncthreads();
    int u = edges[2 * tid], v = edges[2 * tid + 1];
    atomicAdd(&As[u * 32 + v], g_preds[p * M_EDGES + tid]);
    __syncthreads();
    int s = p >> 5;
    int diag = s * 32 + s;
    #pragma unroll
    for (int i = tid; i < 1024; i += 256) {
        float val = As[i];
        if (i == diag) val += 1.f;
        g_A[p * 1024 + i] = val;
    }
}

// ---------------- kernel 4: 50-step power iteration, one warp per pair ----------------
// grid 128 x 256 = 1024 warps
__global__ void power_kernel()
{
    int gtid = blockIdx.x * blockDim.x + threadIdx.x;
    int p    = gtid >> 5;
    int lane = threadIdx.x & 31;
    const float* Ap = g_A + p * 1024;

    float col[32];                       // A[:, lane]
    #pragma unroll
    for (int u = 0; u < 32; u++) col[u] = Ap[u * 32 + lane];

    float x = 1.0f / 32.0f;
    for (int it = 0; it < 50; it++) {
        float acc = 0.f;
        #pragma unroll
        for (int u = 0; u < 32; u++)
            acc = fmaf(__shfl_sync(0xffffffffu, x, u), col[u], acc);
        float ss = acc * acc;
        #pragma unroll
        for (int o = 16; o > 0; o >>= 1)
            ss += __shfl_xor_sync(0xffffffffu, ss, o);
        x = acc / (sqrtf(ss) + EPSF);
    }
    int s = p >> 5, t = p & 31;
    float xs = __shfl_sync(0xffffffffu, x, s);
    float d  = (s != t) ? x / (xs + EPSF) : 0.f;
    g_delta[p * 32 + lane] = d;
}

// ---------------- kernel 5: deterministic reduction + normalize ----------------
__global__ void reduce_kernel(float* __restrict__ out)
{
    __shared__ float red[32][33];
    int v = threadIdx.x, g = threadIdx.y;
    float acc = 0.f;
    #pragma unroll 4
    for (int p = g; p < NPAIR; p += 32) acc += g_delta[p * 32 + v];
    red[g][v] = acc;
    __syncthreads();
    #pragma unroll
    for (int st = 16; st > 0; st >>= 1) {
        if (g < st) red[g][v] += red[g + st][v];
        __syncthreads();
    }
    if (g == 0) {
        float r = red[0][v];
        float tot = r;
        #pragma unroll
        for (int o = 16; o > 0; o >>= 1)
            tot += __shfl_xor_sync(0xffffffffu, tot, o);
        out[v] = r / tot;
    }
}

// ---------------- launch ----------------
extern "C" void kernel_launch(void* const* d_in, const int* in_sizes, int n_in,
                              void* d_out, int out_size)
{
    (void)in_sizes; (void)n_in; (void)out_size;
    // metadata order: num_nodes, node_embeddings, edges, W1,b1, W2,b2, W3,b3, W4,b4
    const float* emb   = (const float*)d_in[1];
    const int*   edges = (const int*)  d_in[2];
    const float* W1 = (const float*)d_in[3];
    const float* b1 = (const float*)d_in[4];
    const float* W2 = (const float*)d_in[5];
    const float* b2 = (const float*)d_in[6];
    const float* W3 = (const float*)d_in[7];
    const float* b3 = (const float*)d_in[8];
    const float* W4 = (const float*)d_in[9];
    const float* b4 = (const float*)d_in[10];
    float* out = (float*)d_out;

    prep_kernel   <<<160, 256>>>(emb, edges, W1, b1);
    mlp_kernel    <<<4096, 256>>>(W2, b2, W3, b3, W4, b4);
    scatter_kernel<<<1024, 256>>>(edges);
    power_kernel  <<<128, 256>>>();
    reduce_kernel <<<1, dim3(32, 32)>>>(out);
}

// round 2
// speedup vs baseline: 1.1470x; 1.1470x over previous
#include <cuda_runtime.h>

// Problem constants (fixed by the dataset)
#define N_NODES 32
#define M_EDGES 256
#define D_EMB   32
#define H1 128   // layer-1 width (= 4*d)
#define H2 256
#define H3 128
#define NPAIR 1024          // n*n
#define TM 64               // edge rows per CTA tile
#define HS_PAD 68           // padded row stride for Hs (float4-aligned, reduces conflicts)
#define EPSF 1e-9f

typedef unsigned long long u64;

// ---- f32x2 packed-math helpers (sm_103a FFMA2 — only reachable via PTX) ----
__device__ __forceinline__ u64 pack2(float lo, float hi) {
    u64 r; asm("mov.b64 %0, {%1, %2};" : "=l"(r) : "f"(lo), "f"(hi)); return r;
}
__device__ __forceinline__ void fma2(u64& d, u64 a, u64 b) {
    asm("fma.rn.f32x2 %0, %1, %2, %0;" : "+l"(d) : "l"(a), "l"(b));
}
__device__ __forceinline__ float2 unpack2(u64 v) {
    float2 f; asm("mov.b64 {%0, %1}, %2;" : "=f"(f.x), "=f"(f.y) : "l"(v)); return f;
}

// ---------------- scratch (no allocations allowed) ----------------
__device__ float g_aT[H1 * N_NODES];    // a[k][s]  : emb[s] @ W1[0:32]
__device__ float g_bT[H1 * N_NODES];    // b[k][t]  : emb[t] @ W1[32:64]
__device__ float g_cT[H1 * M_EDGES];    // c[k][e]  : emb[u]@W1[64:96] + emb[v]@W1[96:128] + b1
__device__ float g_preds[NPAIR * M_EDGES];
__device__ float g_A[NPAIR * N_NODES * N_NODES];
__device__ float g_delta[NPAIR * N_NODES];

// ---------------- kernel 1: factored layer-1 partials ----------------
__global__ void prep_kernel(const float* __restrict__ emb,
                            const int*   __restrict__ edges,
                            const float* __restrict__ W1,
                            const float* __restrict__ b1)
{
    int idx = blockIdx.x * blockDim.x + threadIdx.x;
    if (idx < 2 * H1 * N_NODES) {
        int sec = idx >> 12;            // 0: aT, 1: bT
        int r   = idx & 4095;
        int k = r >> 5, s = r & 31;
        const float* w = W1 + (sec ? (32 * H1) : 0) + k;
        float acc = 0.f;
        #pragma unroll
        for (int j = 0; j < D_EMB; j++)
            acc = fmaf(emb[s * D_EMB + j], w[j * H1], acc);
        (sec ? g_bT : g_aT)[k * N_NODES + s] = acc;
    } else {
        int r = idx - 2 * H1 * N_NODES;       // [0, 32768)
        int k = r >> 8, e = r & 255;
        int u = edges[2 * e], v = edges[2 * e + 1];
        const float* wu = W1 + 64 * H1 + k;
        const float* wv = W1 + 96 * H1 + k;
        float acc = b1[k];
        #pragma unroll
        for (int j = 0; j < D_EMB; j++) {
            acc = fmaf(emb[u * D_EMB + j], wu[j * H1], acc);
            acc = fmaf(emb[v * D_EMB + j], wv[j * H1], acc);
        }
        g_cT[k * M_EDGES + e] = acc;
    }
}

// ---------------- kernel 2: fused MLP (layers 2,3,4), f32x2 packed ----------------
// One CTA = one (s,t) pair x 64 edge rows.  grid = 4096, 256 threads.
// Thread micro-tile: 4 rows (tm) x 8 cols (tn), cols processed as 4 f32x2 pairs.
__global__ void __launch_bounds__(256)
mlp_kernel(const float* __restrict__ W2, const float* __restrict__ b2,
           const float* __restrict__ W3, const float* __restrict__ b3,
           const float* __restrict__ W4, const float* __restrict__ b4)
{
    __shared__ __align__(16) float Hs[H1][HS_PAD];  // K x M activation tile
    __shared__ __align__(16) float Bs[16][128];     // K-slice of weights (16 rows)
    __shared__ float red[16][64];                   // layer-4 reduction

    const int tid  = threadIdx.x;
    const int tm   = tid & 15;
    const int tn   = tid >> 4;
    const int bid  = blockIdx.x;
    const int pair = bid >> 2;
    const int eb   = (bid & 3) * TM;
    const int s    = pair >> 5;
    const int t    = pair & 31;

    u64 acc3[4][4];
    #pragma unroll
    for (int i = 0; i < 4; i++)
        #pragma unroll
        for (int jp = 0; jp < 4; jp++) acc3[i][jp] = 0ull;

    for (int kc = 0; kc < 2; kc++) {
        // ---- (re)build h1 tile:  Hs[k][row] = relu(a[s][k]+b[t][k]+c[e][k]) ----
        __syncthreads();   // previous chunk done reading Hs
        #pragma unroll 4
        for (int i = tid; i < H1 * TM; i += 256) {
            int k = i >> 6, row = i & 63;
            float v = g_aT[k * N_NODES + s] + g_bT[k * N_NODES + t]
                    + g_cT[k * M_EDGES + eb + row];
            Hs[k][row] = fmaxf(v, 0.f);
        }

        // ---- layer 2 chunk:  acc2 = h1 @ W2[:, kc*128 : kc*128+128] ----
        u64 acc2[4][4];
        #pragma unroll
        for (int i = 0; i < 4; i++)
            #pragma unroll
            for (int jp = 0; jp < 4; jp++) acc2[i][jp] = 0ull;

        const float* gB2 = W2 + kc * 128;
        for (int k0 = 0; k0 < H1; k0 += 16) {
            __syncthreads();
            {
                int r = tid >> 4, c = (tid & 15) * 8;
                *(float4*)&Bs[r][c]     = *(const float4*)(gB2 + (k0 + r) * H2 + c);
                *(float4*)&Bs[r][c + 4] = *(const float4*)(gB2 + (k0 + r) * H2 + c + 4);
            }
            __syncthreads();
            #pragma unroll
            for (int kk = 0; kk < 16; kk++) {
                float4 a4 = *(const float4*)&Hs[k0 + kk][tm * 4];
                u64 ad[4];
                ad[0] = pack2(a4.x, a4.x); ad[1] = pack2(a4.y, a4.y);
                ad[2] = pack2(a4.z, a4.z); ad[3] = pack2(a4.w, a4.w);
                ulonglong2 b01 = *(const ulonglong2*)&Bs[kk][tn * 8];
                ulonglong2 b23 = *(const ulonglong2*)&Bs[kk][tn * 8 + 4];
                u64 bp[4] = {b01.x, b01.y, b23.x, b23.y};
                #pragma unroll
                for (int i = 0; i < 4; i++)
                    #pragma unroll
                    for (int jp = 0; jp < 4; jp++)
                        fma2(acc2[i][jp], ad[i], bp[jp]);
            }
        }

        // ---- epilogue: h2 chunk -> Hs (transposed store, K2 x M) ----
        __syncthreads();   // everyone done reading h1
        #pragma unroll
        for (int jp = 0; jp < 4; jp++) {
            int j0 = tn * 8 + 2 * jp;
            float bx = b2[kc * 128 + j0], by = b2[kc * 128 + j0 + 1];
            #pragma unroll
            for (int i = 0; i < 4; i++) {
                float2 f = unpack2(acc2[i][jp]);
                Hs[j0][tm * 4 + i]     = fmaxf(f.x + bx, 0.f);
                Hs[j0 + 1][tm * 4 + i] = fmaxf(f.y + by, 0.f);
            }
        }

        // ---- layer 3 chunk:  acc3 += h2c @ W3[kc*128 : kc*128+128, :] ----
        const float* gB3 = W3 + kc * 128 * H3;
        for (int k0 = 0; k0 < 128; k0 += 16) {
            __syncthreads();
            {
                int r = tid >> 4, c = (tid & 15) * 8;
                *(float4*)&Bs[r][c]     = *(const float4*)(gB3 + (k0 + r) * H3 + c);
                *(float4*)&Bs[r][c + 4] = *(const float4*)(gB3 + (k0 + r) * H3 + c + 4);
            }
            __syncthreads();
            #pragma unroll
            for (int kk = 0; kk < 16; kk++) {
                float4 a4 = *(const float4*)&Hs[k0 + kk][tm * 4];
                u64 ad[4];
                ad[0] = pack2(a4.x, a4.x); ad[1] = pack2(a4.y, a4.y);
                ad[2] = pack2(a4.z, a4.z); ad[3] = pack2(a4.w, a4.w);
                ulonglong2 b01 = *(const ulonglong2*)&Bs[kk][tn * 8];
                ulonglong2 b23 = *(const ulonglong2*)&Bs[kk][tn * 8 + 4];
                u64 bp[4] = {b01.x, b01.y, b23.x, b23.y};
                #pragma unroll
                for (int i = 0; i < 4; i++)
                    #pragma unroll
                    for (int jp = 0; jp < 4; jp++)
                        fma2(acc3[i][jp], ad[i], bp[jp]);
            }
        }
    }

    // ---- layer 4: pred = relu(h3) @ W4 + b4, reduce over tn via smem ----
    float part[4] = {0.f, 0.f, 0.f, 0.f};
    #pragma unroll
    for (int jp = 0; jp < 4; jp++) {
        int j0 = tn * 8 + 2 * jp;
        float b3x = b3[j0], b3y = b3[j0 + 1];
        float w4x = W4[j0], w4y = W4[j0 + 1];
        #pragma unroll
        for (int i = 0; i < 4; i++) {
            float2 f = unpack2(acc3[i][jp]);
            part[i] = fmaf(fmaxf(f.x + b3x, 0.f), w4x, part[i]);
            part[i] = fmaf(fmaxf(f.y + b3y, 0.f), w4y, part[i]);
        }
    }
    __syncthreads();
    #pragma unroll
    for (int i = 0; i < 4; i++) red[tn][tm * 4 + i] = part[i];
    __syncthreads();
    #pragma unroll
    for (int st = 8; st > 0; st >>= 1) {
        if (tn < st) {
            #pragma unroll
            for (int i = 0; i < 4; i++)
                red[tn][tm * 4 + i] += red[tn + st][tm * 4 + i];
        }
        __syncthreads();
    }
    if (tn == 0) {
        float b4v = b4[0];
        #pragma unroll
        for (int i = 0; i < 4; i++)
            g_preds[pair * M_EDGES + eb + tm * 4 + i] = red[0][tm * 4 + i] + b4v;
    }
}

// ---------------- kernel 3: scatter preds into routing matrices ----------------
__global__ void scatter_kernel(const int* __restrict__ edges)
{
    __shared__ float As[N_NODES * N_NODES];
    int p = blockIdx.x, tid = threadIdx.x;
    #pragma unroll
    for (int i = tid; i < 1024; i += 256) As[i] = 0.f;
    __syncthreads();
    int u = edges[2 * tid], v = edges[2 * tid + 1];
    atomicAdd(&As[u * 32 + v], g_preds[p * M_EDGES + tid]);
    __syncthreads();
    int s = p >> 5;
    int diag = s * 32 + s;
    #pragma unroll
    for (int i = tid; i < 1024; i += 256) {
        float val = As[i];
        if (i == diag) val += 1.f;
        g_A[p * 1024 + i] = val;
    }
}

// ---------------- kernel 4: 50-step power iteration, one warp per pair ----------------
__global__ void power_kernel()
{
    int gtid = blockIdx.x * blockDim.x + threadIdx.x;
    int p    = gtid >> 5;
    int lane = threadIdx.x & 31;
    const float* Ap = g_A + p * 1024;

    float col[32];                       // A[:, lane]
    #pragma unroll
    for (int u = 0; u < 32; u++) col[u] = Ap[u * 32 + lane];

    float x = 1.0f / 32.0f;
    for (int it = 0; it < 50; it++) {
        float acc = 0.f;
        #pragma unroll
        for (int u = 0; u < 32; u++)
            acc = fmaf(__shfl_sync(0xffffffffu, x, u), col[u], acc);
        float ss = acc * acc;
        #pragma unroll
        for (int o = 16; o > 0; o >>= 1)
            ss += __shfl_xor_sync(0xffffffffu, ss, o);
        x = acc / (sqrtf(ss) + EPSF);
    }
    int s = p >> 5, t = p & 31;
    float xs = __shfl_sync(0xffffffffu, x, s);
    float d  = (s != t) ? x / (xs + EPSF) : 0.f;
    g_delta[p * 32 + lane] = d;
}

// ---------------- kernel 5: deterministic reduction + normalize ----------------
__global__ void reduce_kernel(float* __restrict__ out)
{
    __shared__ float red[32][33];
    int v = threadIdx.x, g = threadIdx.y;
    float acc = 0.f;
    #pragma unroll 4
    for (int p = g; p < NPAIR; p += 32) acc += g_delta[p * 32 + v];
    red[g][v] = acc;
    __syncthreads();
    #pragma unroll
    for (int st = 16; st > 0; st >>= 1) {
        if (g < st) red[g][v] += red[g + st][v];
        __syncthreads();
    }
    if (g == 0) {
        float r = red[0][v];
        float tot = r;
        #pragma unroll
        for (int o = 16; o > 0; o >>= 1)
            tot += __shfl_xor_sync(0xffffffffu, tot, o);
        out[v] = r / tot;
    }
}

// ---------------- launch ----------------
extern "C" void kernel_launch(void* const* d_in, const int* in_sizes, int n_in,
                              void* d_out, int out_size)
{
    (void)in_sizes; (void)n_in; (void)out_size;
    const float* emb   = (const float*)d_in[1];
    const int*   edges = (const int*)  d_in[2];
    const float* W1 = (const float*)d_in[3];
    const float* b1 = (const float*)d_in[4];
    const float* W2 = (const float*)d_in[5];
    const float* b2 = (const float*)d_in[6];
    const float* W3 = (const float*)d_in[7];
    const float* b3 = (const float*)d_in[8];
    const float* W4 = (const float*)d_in[9];
    const float* b4 = (const float*)d_in[10];
    float* out = (float*)d_out;

    prep_kernel   <<<160, 256>>>(emb, edges, W1, b1);
    mlp_kernel    <<<4096, 256>>>(W2, b2, W3, b3, W4, b4);
    scatter_kernel<<<1024, 256>>>(edges);
    power_kernel  <<<128, 256>>>();
    reduce_kernel <<<1, dim3(32, 32)>>>(out);
}

// round 5
// speedup vs baseline: 1.9684x; 1.7161x over previous
#include <cuda_runtime.h>
#include <cuda_bf16.h>
#include <cstdint>

#define N_NODES 32
#define M_EDGES 256
#define H1 128
#define H2 256
#define H3 128
#define NPAIR 1024
#define EPSF 1e-9f

typedef uint32_t u32;

// ---------------- scratch (no allocations allowed) ----------------
__device__ float g_aT[H1 * N_NODES];
__device__ float g_bT[H1 * N_NODES];
__device__ float g_cT[H1 * M_EDGES];
__device__ float g_preds[NPAIR * M_EDGES];
__device__ float g_A[NPAIR * N_NODES * N_NODES];
__device__ float g_delta[NPAIR * N_NODES];
// Pre-split, pre-transposed weight images: [chunk][hi=0/lo=1][n*128 + k]
__device__ __nv_bfloat16 g_B2sw[2][2][128 * 128];   // W2^T: n = out col, k = in
__device__ __nv_bfloat16 g_B3sw[2][2][128 * 128];   // W3^T: n = out col, k = in (chunked over K)

// ---------------- smem layout (byte offsets; row stride 272B = 136 bf16) ----------------
#define STRIDE_B 272
#define TILE_B   (128 * STRIDE_B)     // 34816
#define SM_A1H 0
#define SM_A1L (SM_A1H + TILE_B)
#define SM_A2H (SM_A1L + TILE_B)
#define SM_A2L (SM_A2H + TILE_B)
#define SM_BH  (SM_A2L + TILE_B)
#define SM_BL  (SM_BH + TILE_B)
#define SM_RED (SM_BL + TILE_B)       // float[4][128]
#define SM_TOTAL (SM_RED + 4 * 128 * 4)

// ---------------- PTX helpers (plain sm_80+ features only) ----------------
__device__ __forceinline__ u32 smem_u32(const void* p) {
    u32 a; asm("{ .reg .u64 t; cvta.to.shared.u64 t, %1; cvt.u32.u64 %0, t; }" : "=r"(a) : "l"(p));
    return a;
}
__device__ __forceinline__ void ldm_x4(u32 r[4], u32 addr) {
    asm volatile("ldmatrix.sync.aligned.m8n8.x4.shared.b16 {%0,%1,%2,%3}, [%4];"
                 : "=r"(r[0]), "=r"(r[1]), "=r"(r[2]), "=r"(r[3]) : "r"(addr));
}
__device__ __forceinline__ void mma16816(float c[4], const u32 a[4], const u32 b[2]) {
    asm volatile("mma.sync.aligned.m16n8k16.row.col.f32.bf16.bf16.f32 "
                 "{%0,%1,%2,%3}, {%4,%5,%6,%7}, {%8,%9}, {%0,%1,%2,%3};"
                 : "+f"(c[0]), "+f"(c[1]), "+f"(c[2]), "+f"(c[3])
                 : "r"(a[0]), "r"(a[1]), "r"(a[2]), "r"(a[3]), "r"(b[0]), "r"(b[1]));
}
__device__ __forceinline__ __nv_bfloat162 split_hi(float v0, float v1, __nv_bfloat162& lo) {
    __nv_bfloat162 hi;
    hi.x = __float2bfloat16(v0); hi.y = __float2bfloat16(v1);
    lo.x = __float2bfloat16(v0 - __bfloat162float(hi.x));
    lo.y = __float2bfloat16(v1 - __bfloat162float(hi.y));
    return hi;
}

// ---------------- kernel 1: factored layer-1 partials ----------------
__global__ void prep_kernel(const float* __restrict__ emb,
                            const int*   __restrict__ edges,
                            const float* __restrict__ W1,
                            const float* __restrict__ b1)
{
    int idx = blockIdx.x * blockDim.x + threadIdx.x;
    if (idx < 2 * H1 * N_NODES) {
        int sec = idx >> 12;
        int r = idx & 4095;
        int k = r >> 5, s = r & 31;
        const float* w = W1 + (sec ? (32 * H1) : 0) + k;
        float acc = 0.f;
        #pragma unroll
        for (int j = 0; j < 32; j++)
            acc = fmaf(emb[s * 32 + j], w[j * H1], acc);
        (sec ? g_bT : g_aT)[k * N_NODES + s] = acc;
    } else {
        int r = idx - 2 * H1 * N_NODES;
        int k = r >> 8, e = r & 255;
        int u = edges[2 * e], v = edges[2 * e + 1];
        const float* wu = W1 + 64 * H1 + k;
        const float* wv = W1 + 96 * H1 + k;
        float acc = b1[k];
        #pragma unroll
        for (int j = 0; j < 32; j++) {
            acc = fmaf(emb[u * 32 + j], wu[j * H1], acc);
            acc = fmaf(emb[v * 32 + j], wv[j * H1], acc);
        }
        g_cT[k * M_EDGES + e] = acc;
    }
}

// ---------------- kernel 1b: split + transpose weights to [N][K] bf16 hi/lo ----------------
__global__ void wprep_kernel(const float* __restrict__ W2, const float* __restrict__ W3)
{
    int idx = blockIdx.x * blockDim.x + threadIdx.x;   // 65536 total
    int sec = idx >> 15;
    int r = idx & 32767;
    int p = r >> 14;
    int e = r & 16383;
    int n = e >> 7, k = e & 127;
    float w = (sec == 0) ? W2[k * H2 + p * 128 + n]          // W2 [128k][256n]
                         : W3[(p * 128 + k) * H3 + n];       // W3 [256k][128n]
    __nv_bfloat16 hi = __float2bfloat16(w);
    __nv_bfloat16 lo = __float2bfloat16(w - __bfloat162float(hi));
    if (sec == 0) { g_B2sw[p][0][n * 128 + k] = hi; g_B2sw[p][1][n * 128 + k] = lo; }
    else          { g_B3sw[p][0][n * 128 + k] = hi; g_B3sw[p][1][n * 128 + k] = lo; }
}

// ---------------- kernel 2: fused MLP via ldmatrix + mma.sync bf16 (3-term split) ----------------
__device__ __forceinline__ void copyB(unsigned char* smp,
                                      const __nv_bfloat16* __restrict__ srcH,
                                      const __nv_bfloat16* __restrict__ srcL, int tid)
{
    const float4* sH = (const float4*)srcH;
    const float4* sL = (const float4*)srcL;
    #pragma unroll
    for (int i = 0; i < 8; i++) {
        int f = tid + i * 256;             // 2048 float4 per 32KB image
        int row = f >> 4, c16 = f & 15;
        *(float4*)(smp + SM_BH + row * STRIDE_B + c16 * 16) = sH[f];
        *(float4*)(smp + SM_BL + row * STRIDE_B + c16 * 16) = sL[f];
    }
}

// One GEMM phase: acc[mt][nt][4] += 3-term split of A[128x128] @ B^T[128x128]
__device__ __forceinline__ void mma_phase(float acc[4][4][4],
                                          u32 aH, u32 aL, u32 bH, u32 bL,
                                          int m0, int n0, int lane)
{
    const int arow = (lane & 7) + ((lane >> 3) & 1) * 8;
    const int akof = (lane >> 4) * 8;
    const int bnof = ((lane >> 4) << 3) + (lane & 7);
    const int bkof = ((lane >> 3) & 1) << 3;
    const u32 aoH = aH + (m0 + arow) * STRIDE_B + akof * 2;
    const u32 aoL = aL + (m0 + arow) * STRIDE_B + akof * 2;
    const u32 boH = bH + (n0 + bnof) * STRIDE_B + bkof * 2;
    const u32 boL = bL + (n0 + bnof) * STRIDE_B + bkof * 2;

    #pragma unroll
    for (int ks = 0; ks < 8; ks++) {
        const u32 kb = ks * 32;                     // 16 bf16 = 32 bytes
        u32 ah[4][4], al[4][4];
        #pragma unroll
        for (int mt = 0; mt < 4; mt++) {
            ldm_x4(ah[mt], aoH + mt * 16 * STRIDE_B + kb);
            ldm_x4(al[mt], aoL + mt * 16 * STRIDE_B + kb);
        }
        u32 bh[2][4], bl[2][4];
        #pragma unroll
        for (int np = 0; np < 2; np++) {
            ldm_x4(bh[np], boH + np * 16 * STRIDE_B + kb);
            ldm_x4(bl[np], boL + np * 16 * STRIDE_B + kb);
        }
        #pragma unroll
        for (int mt = 0; mt < 4; mt++)
            #pragma unroll
            for (int nt = 0; nt < 4; nt++) {
                const u32* Bh = &bh[nt >> 1][(nt & 1) * 2];
                const u32* Bl = &bl[nt >> 1][(nt & 1) * 2];
                mma16816(acc[mt][nt], ah[mt], Bh);   // hi*hi
                mma16816(acc[mt][nt], ah[mt], Bl);   // hi*lo
                mma16816(acc[mt][nt], al[mt], Bh);   // lo*hi
            }
    }
}

// h2 epilogue: +b2, relu, split hi/lo into A2 buffer (chunk-local cols 0..127)
__device__ __forceinline__ void epilogue_h2(float acc[4][4][4], unsigned char* smp,
                                            const float* __restrict__ b2p,
                                            int m0, int n0, int lane)
{
    #pragma unroll
    for (int nt = 0; nt < 4; nt++) {
        int c = n0 + nt * 8 + (lane & 3) * 2;
        float bx = __ldg(&b2p[c]), by = __ldg(&b2p[c + 1]);
        #pragma unroll
        for (int mt = 0; mt < 4; mt++) {
            int r0 = m0 + mt * 16 + (lane >> 2);
            #pragma unroll
            for (int h = 0; h < 2; h++) {
                int row = r0 + h * 8;
                float v0 = fmaxf(acc[mt][nt][h * 2 + 0] + bx, 0.f);
                float v1 = fmaxf(acc[mt][nt][h * 2 + 1] + by, 0.f);
                __nv_bfloat162 lo, hi = split_hi(v0, v1, lo);
                *(__nv_bfloat162*)(smp + SM_A2H + row * STRIDE_B + c * 2) = hi;
                *(__nv_bfloat162*)(smp + SM_A2L + row * STRIDE_B + c * 2) = lo;
            }
        }
    }
}

__global__ void __launch_bounds__(256, 1)
mlp_mma_kernel(const float* __restrict__ b2, const float* __restrict__ b3,
               const float* __restrict__ W4, const float* __restrict__ b4)
{
    extern __shared__ unsigned char smp[];
    const u32 sb = smem_u32(smp);
    const int tid  = threadIdx.x;
    const int wid  = tid >> 5;
    const int lane = tid & 31;
    const int wm   = wid >> 2;          // 0..1 -> m offset 0/64
    const int wn   = wid & 3;           // 0..3 -> n offset 0/32/64/96
    const int m0 = wm * 64, n0 = wn * 32;
    const int bid  = blockIdx.x;
    const int pair = bid >> 1;
    const int eb   = (bid & 1) * 128;
    const int s = pair >> 5, t = pair & 31;

    // ---- build h1 half-tile [128 rows x 128 k], split hi/lo ----
    {
        int k0 = (tid & 63) * 2;
        float base0 = g_aT[k0 * N_NODES + s] + g_bT[k0 * N_NODES + t];
        float base1 = g_aT[(k0 + 1) * N_NODES + s] + g_bT[(k0 + 1) * N_NODES + t];
        int r0 = tid >> 6;
        #pragma unroll 8
        for (int it = 0; it < 32; it++) {
            int row = r0 + it * 4;
            float v0 = fmaxf(base0 + g_cT[k0 * M_EDGES + eb + row], 0.f);
            float v1 = fmaxf(base1 + g_cT[(k0 + 1) * M_EDGES + eb + row], 0.f);
            __nv_bfloat162 lo, hi = split_hi(v0, v1, lo);
            *(__nv_bfloat162*)(smp + SM_A1H + row * STRIDE_B + k0 * 2) = hi;
            *(__nv_bfloat162*)(smp + SM_A1L + row * STRIDE_B + k0 * 2) = lo;
        }
    }

    float acc3[4][4][4];
    #pragma unroll
    for (int mt = 0; mt < 4; mt++)
        #pragma unroll
        for (int nt = 0; nt < 4; nt++)
            #pragma unroll
            for (int i = 0; i < 4; i++) acc3[mt][nt][i] = 0.f;

    // ---- phase 1: layer2 N-chunk 0 ----
    copyB(smp, g_B2sw[0][0], g_B2sw[0][1], tid);
    __syncthreads();
    {
        float acc2[4][4][4];
        #pragma unroll
        for (int mt = 0; mt < 4; mt++)
            #pragma unroll
            for (int nt = 0; nt < 4; nt++)
                #pragma unroll
                for (int i = 0; i < 4; i++) acc2[mt][nt][i] = 0.f;
        mma_phase(acc2, sb + SM_A1H, sb + SM_A1L, sb + SM_BH, sb + SM_BL, m0, n0, lane);
        epilogue_h2(acc2, smp, b2 + 0 * 128, m0, n0, lane);
    }
    __syncthreads();

    // ---- phase 2: layer3 K-chunk 0 (reads A2) ----
    copyB(smp, g_B3sw[0][0], g_B3sw[0][1], tid);
    __syncthreads();
    mma_phase(acc3, sb + SM_A2H, sb + SM_A2L, sb + SM_BH, sb + SM_BL, m0, n0, lane);
    __syncthreads();

    // ---- phase 3: layer2 N-chunk 1 ----
    copyB(smp, g_B2sw[1][0], g_B2sw[1][1], tid);
    __syncthreads();
    {
        float acc2[4][4][4];
        #pragma unroll
        for (int mt = 0; mt < 4; mt++)
            #pragma unroll
            for (int nt = 0; nt < 4; nt++)
                #pragma unroll
                for (int i = 0; i < 4; i++) acc2[mt][nt][i] = 0.f;
        mma_phase(acc2, sb + SM_A1H, sb + SM_A1L, sb + SM_BH, sb + SM_BL, m0, n0, lane);
        epilogue_h2(acc2, smp, b2 + 1 * 128, m0, n0, lane);
    }
    __syncthreads();

    // ---- phase 4: layer3 K-chunk 1 (accumulate into acc3) ----
    copyB(smp, g_B3sw[1][0], g_B3sw[1][1], tid);
    __syncthreads();
    mma_phase(acc3, sb + SM_A2H, sb + SM_A2L, sb + SM_BH, sb + SM_BL, m0, n0, lane);

    // ---- layer 4: pred = relu(h3 + b3) . W4 + b4 ----
    float* red = (float*)(smp + SM_RED);     // [4][128]
    #pragma unroll
    for (int mt = 0; mt < 4; mt++) {
        #pragma unroll
        for (int h = 0; h < 2; h++) {
            float part = 0.f;
            #pragma unroll
            for (int nt = 0; nt < 4; nt++) {
                int c = n0 + nt * 8 + (lane & 3) * 2;
                float h0 = fmaxf(acc3[mt][nt][h * 2 + 0] + __ldg(&b3[c]), 0.f);
                float h1 = fmaxf(acc3[mt][nt][h * 2 + 1] + __ldg(&b3[c + 1]), 0.f);
                part = fmaf(h0, __ldg(&W4[c]), part);
                part = fmaf(h1, __ldg(&W4[c + 1]), part);
            }
            part += __shfl_xor_sync(0xffffffffu, part, 1);
            part += __shfl_xor_sync(0xffffffffu, part, 2);
            if ((lane & 3) == 0) {
                int row = m0 + mt * 16 + (lane >> 2) + h * 8;
                red[wn * 128 + row] = part;
            }
        }
    }
    __syncthreads();
    if (tid < 128) {
        float acc = red[tid] + red[128 + tid] + red[256 + tid] + red[384 + tid];
        g_preds[pair * M_EDGES + eb + tid] = acc + __ldg(&b4[0]);
    }
}

// ---------------- kernel 3: scatter preds into routing matrices ----------------
__global__ void scatter_kernel(const int* __restrict__ edges)
{
    __shared__ float As[1024];
    int p = blockIdx.x, tid = threadIdx.x;
    #pragma unroll
    for (int i = tid; i < 1024; i += 256) As[i] = 0.f;
    __syncthreads();
    int u = edges[2 * tid], v = edges[2 * tid + 1];
    atomicAdd(&As[u * 32 + v], g_preds[p * M_EDGES + tid]);
    __syncthreads();
    int s = p >> 5;
    int diag = s * 32 + s;
    #pragma unroll
    for (int i = tid; i < 1024; i += 256) {
        float val = As[i];
        if (i == diag) val += 1.f;
        g_A[p * 1024 + i] = val;
    }
}

// ---------------- kernel 4: 50-step power iteration ----------------
__global__ void power_kernel()
{
    int gtid = blockIdx.x * blockDim.x + threadIdx.x;
    int p = gtid >> 5;
    int lane = threadIdx.x & 31;
    const float* Ap = g_A + p * 1024;

    float col[32];
    #pragma unroll
    for (int u = 0; u < 32; u++) col[u] = Ap[u * 32 + lane];

    float x = 1.0f / 32.0f;
    for (int it = 0; it < 50; it++) {
        float acc = 0.f;
        #pragma unroll
        for (int u = 0; u < 32; u++)
            acc = fmaf(__shfl_sync(0xffffffffu, x, u), col[u], acc);
        float ss = acc * acc;
        #pragma unroll
        for (int o = 16; o > 0; o >>= 1)
            ss += __shfl_xor_sync(0xffffffffu, ss, o);
        x = acc / (sqrtf(ss) + EPSF);
    }
    int s = p >> 5, t = p & 31;
    float xs = __shfl_sync(0xffffffffu, x, s);
    float d = (s != t) ? x / (xs + EPSF) : 0.f;
    g_delta[p * 32 + lane] = d;
}

// ---------------- kernel 5: deterministic reduction + normalize ----------------
__global__ void reduce_kernel(float* __restrict__ out)
{
    __shared__ float red[32][33];
    int v = threadIdx.x, g = threadIdx.y;
    float acc = 0.f;
    #pragma unroll 4
    for (int p = g; p < NPAIR; p += 32) acc += g_delta[p * 32 + v];
    red[g][v] = acc;
    __syncthreads();
    #pragma unroll
    for (int st = 16; st > 0; st >>= 1) {
        if (g < st) red[g][v] += red[g + st][v];
        __syncthreads();
    }
    if (g == 0) {
        float r = red[0][v];
        float tot = r;
        #pragma unroll
        for (int o = 16; o > 0; o >>= 1)
            tot += __shfl_xor_sync(0xffffffffu, tot, o);
        out[v] = r / tot;
    }
}

// ---------------- launch ----------------
extern "C" void kernel_launch(void* const* d_in, const int* in_sizes, int n_in,
                              void* d_out, int out_size)
{
    (void)in_sizes; (void)n_in; (void)out_size;
    const float* emb   = (const float*)d_in[1];
    const int*   edges = (const int*)  d_in[2];
    const float* W1 = (const float*)d_in[3];
    const float* b1 = (const float*)d_in[4];
    const float* W2 = (const float*)d_in[5];
    const float* b2 = (const float*)d_in[6];
    const float* W3 = (const float*)d_in[7];
    const float* b3 = (const float*)d_in[8];
    const float* W4 = (const float*)d_in[9];
    const float* b4 = (const float*)d_in[10];
    float* out = (float*)d_out;

    static int smem_set = 0;
    if (!smem_set) {
        cudaFuncSetAttribute(mlp_mma_kernel, cudaFuncAttributeMaxDynamicSharedMemorySize, SM_TOTAL);
        smem_set = 1;
    }

    prep_kernel   <<<160, 256>>>(emb, edges, W1, b1);
    wprep_kernel  <<<256, 256>>>(W2, W3);
    mlp_mma_kernel<<<2048, 256, SM_TOTAL>>>(b2, b3, W4, b4);
    scatter_kernel<<<1024, 256>>>(edges);
    power_kernel  <<<128, 256>>>();
    reduce_kernel <<<1, dim3(32, 32)>>>(out);
}